// round 10
// baseline (speedup 1.0000x reference)
#include <cuda_runtime.h>
#include <cstdint>

#define N_BITS 108
#define N_OUT  7
#define TPB    256
#define NWARPS (TPB / 32)

// Row = 108 floats = 432 B = 27 uint4. Values exactly 0.0f/1.0f:
// (word >> 29) & 1 extracts the bit.
// Measured across R5-R9: DRAM traffic is pinned (~535 MB read) by 128B-line
// touch depth regardless of round schedule -> optimize chain depth + L1.
// Stage 1: ONE 128 B round (bits [0,32), 8x LDG.128) resolves ~62% of rows.
// Stage 2: unresolved rows queued in smem; warps drain 1 row/iter with a
// single coalesced load (lanes 0-18 -> words 8-26, 304 B contiguous),
// ballot+shfl pick the first set bit. Iterations independent -> high MLP.

__device__ __forceinline__ unsigned mask4(uint4 w) {
    return ((w.x >> 29) & 1u)
         | (((w.y >> 29) & 1u) << 1)
         | (((w.z >> 29) & 1u) << 2)
         | (((w.w >> 29) & 1u) << 3);
}

__global__ __launch_bounds__(TPB, 8)
void lzd108_kernel(const uint4* __restrict__ X, float* __restrict__ out, int n_rows) {
    __shared__ unsigned short s_pos[TPB];
    __shared__ unsigned short s_q[TPB];
    __shared__ int s_count;

    int tid = threadIdx.x;
    if (tid == 0) s_count = 0;
    __syncthreads();

    size_t brow = (size_t)blockIdx.x * TPB;
    int row = (int)brow + tid;
    int pos = N_BITS;  // 108 = 1101100b == LZC_108 (all-zero row)

    if (row < n_rows) {
        const uint4* p = X + (size_t)row * 27;

        // Stage 1: bits [0,32) — words 0..7, 128 B, 8 independent LDG.128
        unsigned m = 0;
        #pragma unroll
        for (int j = 0; j < 8; ++j) m |= mask4(__ldg(p + j)) << (4 * j);
        if (m) {
            pos = __ffs(m) - 1;
        } else {
            int qi = atomicAdd(&s_count, 1);
            s_q[qi] = (unsigned short)tid;
        }
    }
    s_pos[tid] = (unsigned short)pos;
    __syncthreads();

    // Stage 2: cooperative drain — bits [32,108) = words 8..26 (19 uint4).
    int nq = s_count;
    int lane = tid & 31;
    int wid = tid >> 5;

    for (int it = wid; it < nq; it += NWARPS) {
        int t = s_q[it];
        unsigned mymask = 0;
        if (lane < 19) {
            // one coalesced 304 B span: lanes 0-18 load words 8..26
            mymask = mask4(__ldg(X + (brow + (size_t)t) * 27 + 8 + lane));
        }
        unsigned bal = __ballot_sync(0xFFFFFFFFu, mymask != 0u);
        if (bal) {
            int fl = __ffs(bal) - 1;                       // first lane with a hit
            unsigned wm = __shfl_sync(0xFFFFFFFFu, mymask, fl);
            if (lane == 0)
                s_pos[t] = (unsigned short)(32 + 4 * fl + __ffs(wm) - 1);
        }
        // else: row all-zero past bit 32 -> s_pos stays 108
    }
    __syncthreads();

    // Coalesced output: block writes its 1792 floats contiguously,
    // reconstructing bits from s_pos.
    size_t ob = brow * N_OUT;
    size_t total = (size_t)n_rows * N_OUT;
    #pragma unroll
    for (int i = 0; i < N_OUT; ++i) {
        size_t gi = ob + (size_t)(i * TPB + tid);
        if (gi < total) {
            int local = i * TPB + tid;   // 0..1791
            int r = local / N_OUT;
            int b = local - r * N_OUT;
            out[gi] = (float)((s_pos[r] >> (6 - b)) & 1);
        }
    }
}

extern "C" void kernel_launch(void* const* d_in, const int* in_sizes, int n_in,
                              void* d_out, int out_size) {
    const uint4* X = (const uint4*)d_in[0];
    float* out = (float*)d_out;
    int n_rows = in_sizes[0] / N_BITS;

    int blocks = (n_rows + TPB - 1) / TPB;
    lzd108_kernel<<<blocks, TPB>>>(X, out, n_rows);
}

// round 11
// speedup vs baseline: 1.1978x; 1.1978x over previous
#include <cuda_runtime.h>
#include <cstdint>

#define N_BITS 108
#define N_OUT  7
#define TPB    256
#define NBLK   1216   // ~SMs x 8 resident CTAs: single persistent wave

// Row = 108 floats = 432 B = 27 uint4. Values exactly 0.0f/1.0f:
// (word >> 29) & 1 extracts the bit.
// R9 champion ladder (aligned window, 4 x 128 B rounds) made persistent:
// each block grid-strides over row-tiles, so tile t+1's round-0 loads issue
// while tile t's stragglers drain -> continuous DRAM pressure, no wave
// transitions. s_pos is double-buffered by tile parity -> 1 sync per tile.

__device__ __forceinline__ unsigned mask4(uint4 w) {
    return ((w.x >> 29) & 1u)
         | (((w.y >> 29) & 1u) << 1)
         | (((w.z >> 29) & 1u) << 2)
         | (((w.w >> 29) & 1u) << 3);
}

__global__ __launch_bounds__(TPB, 8)
void lzd108_kernel(const uint4* __restrict__ X, float* __restrict__ out,
                   int n_rows, unsigned lim /* total uint4 count */) {
    __shared__ unsigned short s_pos[2][TPB];

    int tid = threadIdx.x;
    int n_tiles = (n_rows + TPB - 1) / TPB;
    unsigned last = lim - 1u;
    size_t total = (size_t)n_rows * N_OUT;

    int buf = 0;
    for (int tile = blockIdx.x; tile < n_tiles; tile += NBLK, buf ^= 1) {
        size_t brow = (size_t)tile * TPB;
        int row = (int)brow + tid;
        int pos = N_BITS;  // 108 = 1101100b == LZC_108 (all-zero row)

        if (row < n_rows) {
            unsigned w0 = 27u * (unsigned)row;   // uint4 index of row start
            unsigned a0 = w0 & ~3u;              // 64B-aligned window base
            int d = 4 * (int)(w0 & 3u);          // junk floats at window start
            const uint4* p = X + a0;

            int pw = -1;  // first-one in WINDOW floats; row pos = pw - d

            // Round 0: window floats [0,32) — 128 B
            unsigned m = 0;
            #pragma unroll
            for (int j = 0; j < 8; ++j) m |= mask4(__ldg(p + j)) << (4 * j);
            m &= 0xFFFFFFFFu << d;               // drop previous-row junk
            if (m) {
                pw = __ffs(m) - 1;
            } else {
                // Round 1: floats [32,64)
                m = 0;
                #pragma unroll
                for (int j = 0; j < 8; ++j) m |= mask4(__ldg(p + 8 + j)) << (4 * j);
                if (m) {
                    pw = 32 + __ffs(m) - 1;
                } else {
                    // Round 2: floats [64,96)
                    m = 0;
                    #pragma unroll
                    for (int j = 0; j < 8; ++j) m |= mask4(__ldg(p + 16 + j)) << (4 * j);
                    if (m) {
                        pw = 64 + __ffs(m) - 1;
                    } else {
                        // Round 3: floats [96,128), clamped at buffer end.
                        // Valid row floats: window float < 108+d -> bit < 12+d;
                        // clamped duplicates fall outside that mask.
                        m = 0;
                        #pragma unroll
                        for (int j = 0; j < 8; ++j) {
                            unsigned gi = a0 + 24 + j;
                            uint4 w = __ldg(X + min(gi, last));
                            m |= mask4(w) << (4 * j);
                        }
                        m &= (1u << (12 + d)) - 1u;
                        if (m) pw = 96 + __ffs(m) - 1;
                    }
                }
            }
            if (pw >= 0) pos = pw - d;
        }

        s_pos[buf][tid] = (unsigned short)pos;
        __syncthreads();  // also separates this buf's writes from its reuse 2 tiles later

        // Coalesced output: the tile's 1792 floats written contiguously.
        size_t ob = brow * N_OUT;
        #pragma unroll
        for (int i = 0; i < N_OUT; ++i) {
            size_t gi = ob + (size_t)(i * TPB + tid);
            if (gi < total) {
                int local = i * TPB + tid;   // 0..1791
                int r = local / N_OUT;
                int b = local - r * N_OUT;
                out[gi] = (float)((s_pos[buf][r] >> (6 - b)) & 1);
            }
        }
        // no second sync: next tile writes the OTHER buffer; this buffer is
        // next written two tiles from now, after the intervening sync.
    }
}

extern "C" void kernel_launch(void* const* d_in, const int* in_sizes, int n_in,
                              void* d_out, int out_size) {
    const uint4* X = (const uint4*)d_in[0];
    float* out = (float*)d_out;
    int n_rows = in_sizes[0] / N_BITS;
    unsigned lim = (unsigned)(in_sizes[0] / 4);  // total uint4 count

    int n_tiles = (n_rows + TPB - 1) / TPB;
    int blocks = n_tiles < NBLK ? n_tiles : NBLK;
    lzd108_kernel<<<blocks, TPB>>>(X, out, n_rows, lim);
}